// round 10
// baseline (speedup 1.0000x reference)
#include <cuda_runtime.h>
#include <cuda_bf16.h>
#include <cuda_fp16.h>
#include <stdint.h>
#include <math.h>

#define IN_SZ   3072
#define CORE    1024
#define OUT_N   100
#define OUT_PAD 128
#define BATCH   8192
#define LDSROW  80   // smem row stride bytes (64B data + 16 pad), conflict-free LDSM

__device__ int g_mode;     // input dtype: 0=int8,1=f32,2=i32,3=bf16
__device__ int g_use_f16;  // 1 if f16 mma path measured faster

// int8-path scratch
__device__ __align__(16) int8_t g_WiT[CORE * IN_SZ];
__device__ __align__(16) int8_t g_WcT[CORE * CORE];
__device__ __align__(16) int8_t g_WoT[OUT_PAD * CORE];
__device__ __align__(16) int8_t g_in8[(size_t)BATCH * IN_SZ];
__device__ __align__(16) int8_t g_A2[(size_t)BATCH * CORE];
__device__ __align__(16) int8_t g_H2[(size_t)BATCH * CORE];
// f16-path scratch
__device__ __align__(16) __half g_WiTh[CORE * IN_SZ];
__device__ __align__(16) __half g_WcTh[CORE * CORE];
__device__ __align__(16) __half g_WoTh[OUT_PAD * CORE];
__device__ __align__(16) __half g_inH[(size_t)BATCH * IN_SZ];
__device__ __align__(16) __half g_A2h[(size_t)BATCH * CORE];
__device__ __align__(16) __half g_H2h[(size_t)BATCH * CORE];
// shared
__device__ __align__(16) int8_t g_h8[(size_t)BATCH * CORE];
__device__ __align__(16) int    g_bi[CORE];
__device__ __align__(16) int    g_bc[CORE];
__device__ __align__(16) int    g_bo[OUT_PAD];

__device__ __forceinline__ uint32_t smem_u32(const void* p) {
    uint32_t a;
    asm("{ .reg .u64 t; cvta.to.shared.u64 t, %1; cvt.u32.u64 %0, t; }" : "=r"(a) : "l"(p));
    return a;
}
__device__ __forceinline__ void cpasync16(unsigned dst, const void* src) {
    asm volatile("cp.async.cg.shared.global [%0], [%1], 16;" :: "r"(dst), "l"(src));
}

__device__ __forceinline__ int ldval(const void* src, long i, int m) {
    if (m == 0) return (int)((const int8_t*)src)[i];
    if (m == 1) return (int)((const float*)src)[i];
    if (m == 2) return ((const int*)src)[i];
    return (int)__bfloat162float(((const __nv_bfloat16*)src)[i]);
}

__global__ void detect_mode(const void* w, int unit) {
    if (unit == 2) { if (threadIdx.x == 0) g_mode = 3; return; }
    unsigned r = ((const unsigned*)w)[threadIdx.x * 101];
    int vi = (int)r;
    bool okI = (vi >= -10 && vi <= 10);
    float f = __int_as_float(r);
    bool okF = (isfinite(f) && f == truncf(f) && fabsf(f) <= 10.0f &&
                (f == 0.0f || fabsf(f) >= 1.0f));
    bool okB = true;
    for (int h = 0; h < 2; h++) {
        unsigned hf = (h == 0) ? (r & 0xFFFFu) : (r >> 16);
        float fb = __int_as_float(hf << 16);
        if (!(isfinite(fb) && fb == truncf(fb) && fabsf(fb) <= 10.0f &&
              (fb == 0.0f || fabsf(fb) >= 1.0f))) okB = false;
    }
    int aI = __syncthreads_and((int)okI);
    int aF = __syncthreads_and((int)okF);
    int aB = __syncthreads_and((int)okB);
    if (threadIdx.x == 0)
        g_mode = (unit == 4) ? (aI ? 2 : 1) : (aI ? 2 : (aF ? 1 : (aB ? 3 : 0)));
}

// ---- calibration: time f16 mma vs s8 mma issue rate on this silicon ----
__global__ void calib_mma() {
    float fa[4][4];
    int   ia[4][4];
    uint32_t a0 = 0x3C003C00u, a1 = 0x3C003C00u, a2 = 0x3C003C00u, a3 = 0x3C003C00u;
    uint32_t b0 = 0x3C003C00u, b1 = 0x3C003C00u;
    uint32_t s0 = 0x01010101u, s1 = 0x01010101u, s2 = 0x01010101u, s3 = 0x01010101u;
#pragma unroll
    for (int j = 0; j < 4; j++)
#pragma unroll
        for (int k = 0; k < 4; k++) { fa[j][k] = 0.f; ia[j][k] = 0; }

#define MMA_F16(j) asm volatile( \
    "mma.sync.aligned.m16n8k16.row.col.f32.f16.f16.f32 " \
    "{%0,%1,%2,%3}, {%4,%5,%6,%7}, {%8,%9}, {%0,%1,%2,%3};" \
    : "+f"(fa[j][0]), "+f"(fa[j][1]), "+f"(fa[j][2]), "+f"(fa[j][3]) \
    : "r"(a0), "r"(a1), "r"(a2), "r"(a3), "r"(b0), "r"(b1))
#define MMA_S8(j) asm volatile( \
    "mma.sync.aligned.m16n8k32.row.col.s32.s8.s8.s32 " \
    "{%0,%1,%2,%3}, {%4,%5,%6,%7}, {%8,%9}, {%0,%1,%2,%3};" \
    : "+r"(ia[j][0]), "+r"(ia[j][1]), "+r"(ia[j][2]), "+r"(ia[j][3]) \
    : "r"(s0), "r"(s1), "r"(s2), "r"(s3), "r"(s0), "r"(s1))

    // warm up
    for (int it = 0; it < 8; it++) { MMA_F16(0); MMA_S8(0); }
    __syncwarp();
    long long t0 = clock64();
    for (int it = 0; it < 64; it++) { MMA_F16(0); MMA_F16(1); MMA_F16(2); MMA_F16(3); }
    __syncwarp();
    long long t1 = clock64();
    for (int it = 0; it < 64; it++) { MMA_S8(0); MMA_S8(1); MMA_S8(2); MMA_S8(3); }
    __syncwarp();
    long long t2 = clock64();
#undef MMA_F16
#undef MMA_S8
    // f16 mma = 2048 MAC, s8 mma = 4096 MAC: f16 wins iff 2*t_f16 < t_s8
    if (threadIdx.x == 0) {
        long long tf = t1 - t0, ts = t2 - t1;
        g_use_f16 = (2 * tf < ts) ? 1 : 0;
        // consume accumulators so nothing is elided
        if (fa[0][0] == 12345.0f && ia[0][0] == 987654321) g_use_f16 ^= 0;
    }
}

// inputs -> int8 + half
__global__ void conv_in(const void* __restrict__ src, int count) {
    int m = g_mode;
    long i = (long)blockIdx.x * blockDim.x + threadIdx.x;
    if (i >= count) return;
    int v = ldval(src, i, m);
    int8_t v8 = (int8_t)v;
    g_in8[i] = v8;
    g_inH[i] = __float2half((float)v8);
}
// hiddens -> int8 only (epilogue addend)
__global__ void conv_h(const void* __restrict__ src, int count) {
    int m = g_mode;
    long i = (long)blockIdx.x * blockDim.x + threadIdx.x;
    if (m == 0) {
        long n16 = count >> 4;
        if (i < n16) ((int4*)g_h8)[i] = ((const int4*)src)[i];
        return;
    }
    if (i < count) g_h8[i] = (int8_t)ldval(src, i, m);
}

// transpose W+E -> [Npad,K], dual write int8 + half
__global__ void prep_w_t(const void* __restrict__ W, const void* __restrict__ E,
                         int8_t* __restrict__ dstI, __half* __restrict__ dstH,
                         int Kdim, int Ncols) {
    __shared__ int8_t s[32][33];
    const int kb = blockIdx.x * 32, nb = blockIdx.y * 32;
    const int tx = threadIdx.x, ty = threadIdx.y;
    const int m = g_mode;
#pragma unroll
    for (int i = 0; i < 32; i += 8) {
        int k = kb + ty + i, n = nb + tx;
        int8_t v = 0;
        if (n < Ncols) {
            long idx = (long)k * Ncols + n;
            v = (int8_t)(ldval(W, idx, m) + ldval(E, idx, m));
        }
        s[ty + i][tx] = v;
    }
    __syncthreads();
#pragma unroll
    for (int i = 0; i < 32; i += 8) {
        int n = nb + ty + i, k = kb + tx;
        int8_t v = s[tx][ty + i];
        dstI[(size_t)n * Kdim + k] = v;
        dstH[(size_t)n * Kdim + k] = __float2half((float)v);
    }
}

__global__ void prep_bias(const void* bi, const void* ebi, const void* bc,
                          const void* ebc, const void* bo, const void* ebo) {
    int t = blockIdx.x * blockDim.x + threadIdx.x;
    int m = g_mode;
    if (t < CORE) {
        g_bi[t] = (int)(int8_t)(ldval(bi, t, m) + ldval(ebi, t, m));
    } else if (t < 2 * CORE) {
        int i = t - CORE;
        g_bc[i] = (int)(int8_t)(ldval(bc, i, m) + ldval(ebc, i, m));
    } else if (t < 2 * CORE + OUT_PAD) {
        int i = t - 2 * CORE;
        g_bo[i] = (i < OUT_N) ? (int)(int8_t)(ldval(bo, i, m) + ldval(ebo, i, m)) : 0;
    }
}

// ---- shared epilogue ----
template <int LAYER, typename CT>
__device__ __forceinline__ void epi_store(int m, int n, int v, const int* bias,
                                          CT* Cs, void* Dout, const int8_t* H,
                                          int mode_out) {
    int8_t r = (int8_t)(v + bias[n]);
    if (LAYER == 1) {
        r = (int8_t)(r + H[(size_t)m * CORE + n]);
        if (sizeof(CT) == 1) ((int8_t*)Cs)[(size_t)m * CORE + n] = r;
        else                 ((__half*)Cs)[(size_t)m * CORE + n] = __float2half((float)r);
    } else if (LAYER == 2) {
        if (sizeof(CT) == 1) ((int8_t*)Cs)[(size_t)m * CORE + n] = r;
        else                 ((__half*)Cs)[(size_t)m * CORE + n] = __float2half((float)r);
        long oi = (long)m * CORE + n;
        if (mode_out == 3) ((__nv_bfloat16*)Dout)[oi] = __float2bfloat16((float)r);
        else               ((float*)Dout)[oi] = (float)r;
    } else {
        if (n < OUT_N) {
            long oi = (long)BATCH * CORE + (long)m * OUT_N + n;
            if (mode_out == 3) ((__nv_bfloat16*)Dout)[oi] = __float2bfloat16((float)r);
            else               ((float*)Dout)[oi] = (float)r;
        }
    }
}

// ---------------- f16 tensor GEMM: BM=BN=128, BK=32 halves ----------------
template <int LAYER>
__global__ void __launch_bounds__(256, 2)
gemm_f16(const __half* __restrict__ A, const __half* __restrict__ Bt,
         const int* __restrict__ bias, __half* __restrict__ Cs,
         void* __restrict__ Dout, const int8_t* __restrict__ H,
         int K, int mode_out) {
    if (!g_use_f16) return;
    __shared__ __align__(16) int8_t sA[2][128 * LDSROW];
    __shared__ __align__(16) int8_t sB[2][128 * LDSROW];

    const int tid = threadIdx.x, lane = tid & 31, wid = tid >> 5;
    const int wm = (wid & 1) * 64, wn = (wid >> 1) * 32;
    const int m0 = blockIdx.y * 128, n0 = blockIdx.x * 128;
    // loaders: 512 chunks/operand (128 rows x 4 x16B), 2 chunks/thread
    const int rowA = tid >> 1;                 // chunk c = tid -> row tid>>2? use pairs:
    // chunk ids: c and c+256
    const int cA = tid, cB = tid + 256;
    const int rA = cA >> 2, sgA = (cA & 3) * 16;
    const int rB = cB >> 2, sgB = (cB & 3) * 16;
    (void)rowA;

    const unsigned uA0 = smem_u32(&sA[0][0]), uB0 = smem_u32(&sB[0][0]);
    const unsigned stageSz = 128 * LDSROW;

    float acc[4][4][4];
#pragma unroll
    for (int a = 0; a < 4; a++)
#pragma unroll
        for (int b = 0; b < 4; b++)
#pragma unroll
            for (int c = 0; c < 4; c++) acc[a][b][c] = 0.f;

    const int nk = K >> 5;  // 32 halves per tile

#define LOADF(st, kt)                                                              \
    do {                                                                           \
        const unsigned _d = (st) * stageSz;                                        \
        const int _k = (kt) << 5;                                                  \
        cpasync16(uA0 + _d + rA * LDSROW + sgA, A + (size_t)(m0 + rA) * K + _k + (sgA >> 1)); \
        cpasync16(uA0 + _d + rB * LDSROW + sgB, A + (size_t)(m0 + rB) * K + _k + (sgB >> 1)); \
        cpasync16(uB0 + _d + rA * LDSROW + sgA, Bt + (size_t)(n0 + rA) * K + _k + (sgA >> 1)); \
        cpasync16(uB0 + _d + rB * LDSROW + sgB, Bt + (size_t)(n0 + rB) * K + _k + (sgB >> 1)); \
        asm volatile("cp.async.commit_group;");                                    \
    } while (0)

    LOADF(0, 0);
    asm volatile("cp.async.wait_group 0;");
    __syncthreads();

    for (int kt = 0; kt < nk; kt++) {
        const int cur = kt & 1;
        const bool nxt = (kt + 1) < nk;
        if (nxt) LOADF(cur ^ 1, kt + 1);
        const unsigned ab = uA0 + cur * stageSz, bb = uB0 + cur * stageSz;
#pragma unroll
        for (int ks = 0; ks < 64; ks += 32) {      // two k16 sub-steps (32B each)
            uint32_t af[4][4], bf[4][2];
#pragma unroll
            for (int mf = 0; mf < 4; mf++) {
                const unsigned p = ab + (wm + mf * 16 + (lane & 15)) * LDSROW + ks + ((lane >> 4) << 4);
                asm volatile("ldmatrix.sync.aligned.m8n8.x4.shared.b16 {%0,%1,%2,%3}, [%4];"
                             : "=r"(af[mf][0]), "=r"(af[mf][1]), "=r"(af[mf][2]), "=r"(af[mf][3]) : "r"(p));
            }
#pragma unroll
            for (int nf = 0; nf < 4; nf++) {
                const unsigned p = bb + (wn + nf * 8 + (lane & 7)) * LDSROW + ks + (((lane >> 3) & 1) << 4);
                asm volatile("ldmatrix.sync.aligned.m8n8.x2.shared.b16 {%0,%1}, [%2];"
                             : "=r"(bf[nf][0]), "=r"(bf[nf][1]) : "r"(p));
            }
#pragma unroll
            for (int mf = 0; mf < 4; mf++)
#pragma unroll
                for (int nf = 0; nf < 4; nf++)
                    asm volatile("mma.sync.aligned.m16n8k16.row.col.f32.f16.f16.f32 "
                                 "{%0,%1,%2,%3}, {%4,%5,%6,%7}, {%8,%9}, {%0,%1,%2,%3};"
                                 : "+f"(acc[mf][nf][0]), "+f"(acc[mf][nf][1]),
                                   "+f"(acc[mf][nf][2]), "+f"(acc[mf][nf][3])
                                 : "r"(af[mf][0]), "r"(af[mf][1]), "r"(af[mf][2]), "r"(af[mf][3]),
                                   "r"(bf[nf][0]), "r"(bf[nf][1]));
        }
        if (nxt) { asm volatile("cp.async.wait_group 0;"); __syncthreads(); }
    }
#undef LOADF

    const int r = lane >> 2, cq = (lane & 3) * 2;
#pragma unroll
    for (int mf = 0; mf < 4; mf++)
#pragma unroll
        for (int nf = 0; nf < 4; nf++)
#pragma unroll
            for (int half = 0; half < 2; half++) {
                const int m = m0 + wm + mf * 16 + r + half * 8;
                const int n = n0 + wn + nf * 8 + cq;
                epi_store<LAYER>(m, n,     __float2int_rn(acc[mf][nf][half * 2 + 0]), bias, Cs, Dout, H, mode_out);
                epi_store<LAYER>(m, n + 1, __float2int_rn(acc[mf][nf][half * 2 + 1]), bias, Cs, Dout, H, mode_out);
            }
}

// ---------------- s8 GEMM (R8 fallback) ----------------
template <int LAYER>
__global__ void __launch_bounds__(256, 2)
gemm_s8(const int8_t* __restrict__ A, const int8_t* __restrict__ Bt,
        const int* __restrict__ bias, int8_t* __restrict__ Cs,
        void* __restrict__ Dout, const int8_t* __restrict__ H,
        int K, int mode_out) {
    if (g_use_f16) return;
    __shared__ __align__(16) int8_t sA[2][128 * LDSROW];
    __shared__ __align__(16) int8_t sB[2][128 * LDSROW];

    const int tid = threadIdx.x, lane = tid & 31, wid = tid >> 5;
    const int wm = (wid & 1) * 64, wn = (wid >> 1) * 32;
    const int m0 = blockIdx.y * 128, n0 = blockIdx.x * 128;
    const int row1 = tid >> 2, row2 = row1 + 64, seg = (tid & 3) * 16;

    const int8_t* gA1 = A + (size_t)(m0 + row1) * K + seg;
    const int8_t* gA2 = A + (size_t)(m0 + row2) * K + seg;
    const int8_t* gB1 = Bt + (size_t)(n0 + row1) * K + seg;
    const int8_t* gB2 = Bt + (size_t)(n0 + row2) * K + seg;
    const unsigned uA0 = smem_u32(&sA[0][0]), uB0 = smem_u32(&sB[0][0]);
    const unsigned dA1 = row1 * LDSROW + seg, dA2 = row2 * LDSROW + seg;

    int acc[4][4][4];
#pragma unroll
    for (int a = 0; a < 4; a++)
#pragma unroll
        for (int b = 0; b < 4; b++)
#pragma unroll
            for (int c = 0; c < 4; c++) acc[a][b][c] = 0;

    const int nk = K >> 6;
    const unsigned stageSz = 128 * LDSROW;
    cpasync16(uA0 + dA1, gA1); cpasync16(uA0 + dA2, gA2);
    cpasync16(uB0 + dA1, gB1); cpasync16(uB0 + dA2, gB2);
    asm volatile("cp.async.commit_group;");
    asm volatile("cp.async.wait_group 0;");
    __syncthreads();

    for (int kt = 0; kt < nk; kt++) {
        const int cur = kt & 1;
        const bool nxt = (kt + 1) < nk;
        if (nxt) {
            const int off = (kt + 1) << 6;
            const unsigned sbb = (cur ^ 1) * stageSz;
            cpasync16(uA0 + sbb + dA1, gA1 + off); cpasync16(uA0 + sbb + dA2, gA2 + off);
            cpasync16(uB0 + sbb + dA1, gB1 + off); cpasync16(uB0 + sbb + dA2, gB2 + off);
            asm volatile("cp.async.commit_group;");
        }
        const unsigned ab = uA0 + cur * stageSz, bb = uB0 + cur * stageSz;
#pragma unroll
        for (int ks = 0; ks < 64; ks += 32) {
            uint32_t af[4][4], bf[4][2];
#pragma unroll
            for (int mf = 0; mf < 4; mf++) {
                const unsigned p = ab + (wm + mf * 16 + (lane & 15)) * LDSROW + ks + ((lane >> 4) << 4);
                asm volatile("ldmatrix.sync.aligned.m8n8.x4.shared.b16 {%0,%1,%2,%3}, [%4];"
                             : "=r"(af[mf][0]), "=r"(af[mf][1]), "=r"(af[mf][2]), "=r"(af[mf][3]) : "r"(p));
            }
#pragma unroll
            for (int nf = 0; nf < 4; nf++) {
                const unsigned p = bb + (wn + nf * 8 + (lane & 7)) * LDSROW + ks + (((lane >> 3) & 1) << 4);
                asm volatile("ldmatrix.sync.aligned.m8n8.x2.shared.b16 {%0,%1}, [%2];"
                             : "=r"(bf[nf][0]), "=r"(bf[nf][1]) : "r"(p));
            }
#pragma unroll
            for (int mf = 0; mf < 4; mf++)
#pragma unroll
                for (int nf = 0; nf < 4; nf++)
                    asm volatile("mma.sync.aligned.m16n8k32.row.col.s32.s8.s8.s32 "
                                 "{%0,%1,%2,%3}, {%4,%5,%6,%7}, {%8,%9}, {%0,%1,%2,%3};"
                                 : "+r"(acc[mf][nf][0]), "+r"(acc[mf][nf][1]),
                                   "+r"(acc[mf][nf][2]), "+r"(acc[mf][nf][3])
                                 : "r"(af[mf][0]), "r"(af[mf][1]), "r"(af[mf][2]), "r"(af[mf][3]),
                                   "r"(bf[nf][0]), "r"(bf[nf][1]));
        }
        if (nxt) { asm volatile("cp.async.wait_group 0;"); __syncthreads(); }
    }

    const int r = lane >> 2, cq = (lane & 3) * 2;
#pragma unroll
    for (int mf = 0; mf < 4; mf++)
#pragma unroll
        for (int nf = 0; nf < 4; nf++)
#pragma unroll
            for (int half = 0; half < 2; half++) {
                const int m = m0 + wm + mf * 16 + r + half * 8;
                const int n = n0 + wn + nf * 8 + cq;
                epi_store<LAYER>(m, n,     acc[mf][nf][half * 2 + 0], bias, Cs, Dout, H, mode_out);
                epi_store<LAYER>(m, n + 1, acc[mf][nf][half * 2 + 1], bias, Cs, Dout, H, mode_out);
            }
}

extern "C" void kernel_launch(void* const* d_in, const int* in_sizes, int n_in,
                              void* d_out, int out_size) {
    int idx[64];
    int cnt = (n_in < 64) ? n_in : 64;
    for (int i = 0; i < cnt; i++) idx[i] = i;
    for (int a = 1; a < cnt; a++) {
        int t = idx[a], b = a - 1;
        while (b >= 0 && in_sizes[idx[b]] < in_sizes[t]) { idx[b + 1] = idx[b]; b--; }
        idx[b + 1] = t;
    }
    const void *inputs = 0, *hiddens = 0, *Wi = 0, *ei = 0, *Wc = 0, *ec = 0;
    const void *Wo = 0, *eo = 0, *bo = 0, *ebo = 0;
    const void *bi = 0, *bc = 0, *ebi = 0, *ebc = 0;
    long unit = 1;
    if (cnt >= 14) {
        inputs = d_in[idx[0]]; hiddens = d_in[idx[1]];
        Wi = d_in[idx[2]]; ei = d_in[idx[3]];
        Wc = d_in[idx[4]]; ec = d_in[idx[5]];
        Wo = d_in[idx[6]]; eo = d_in[idx[7]];
        bo = d_in[idx[12]]; ebo = d_in[idx[13]];
        bool alpha = (idx[4] < idx[2]);
        if (alpha) { bc = d_in[idx[8]]; bi = d_in[idx[9]]; ebc = d_in[idx[10]]; ebi = d_in[idx[11]]; }
        else       { bi = d_in[idx[8]]; bc = d_in[idx[9]]; ebi = d_in[idx[10]]; ebc = d_in[idx[11]]; }
        unit = (long)in_sizes[idx[0]] / ((long)BATCH * IN_SZ);
        if (unit < 1) unit = 1;
    } else {
        Wi = d_in[0]; bi = d_in[1]; Wc = d_in[2]; bc = d_in[3];
        Wo = d_in[4]; bo = d_in[5]; ei = d_in[6]; ebi = d_in[7];
        ec = d_in[8]; ebc = d_in[9]; eo = d_in[10]; ebo = d_in[11];
        inputs = d_in[12]; hiddens = d_in[13];
    }
    const long total_out = (long)BATCH * CORE + (long)BATCH * OUT_N;
    int mode_out = 1;
    if ((long)out_size == 2 * total_out) mode_out = 3;

    void *pWiT, *pWcT, *pWoT, *pWiTh, *pWcTh, *pWoTh;
    void *pbi, *pbc, *pbo, *pin8, *pinH, *ph8, *pA2, *pA2h, *pH2, *pH2h;
    cudaGetSymbolAddress(&pWiT, g_WiT);   cudaGetSymbolAddress(&pWiTh, g_WiTh);
    cudaGetSymbolAddress(&pWcT, g_WcT);   cudaGetSymbolAddress(&pWcTh, g_WcTh);
    cudaGetSymbolAddress(&pWoT, g_WoT);   cudaGetSymbolAddress(&pWoTh, g_WoTh);
    cudaGetSymbolAddress(&pbi, g_bi);
    cudaGetSymbolAddress(&pbc, g_bc);
    cudaGetSymbolAddress(&pbo, g_bo);
    cudaGetSymbolAddress(&pin8, g_in8);   cudaGetSymbolAddress(&pinH, g_inH);
    cudaGetSymbolAddress(&ph8, g_h8);
    cudaGetSymbolAddress(&pA2, g_A2);     cudaGetSymbolAddress(&pA2h, g_A2h);
    cudaGetSymbolAddress(&pH2, g_H2);     cudaGetSymbolAddress(&pH2h, g_H2h);

    dim3 tb(32, 8);
    detect_mode<<<1, 256>>>(Wi, (int)unit);
    calib_mma<<<1, 32>>>();
    conv_in<<<(BATCH * IN_SZ + 255) / 256, 256>>>(inputs, BATCH * IN_SZ);
    conv_h<<<(BATCH * CORE + 255) / 256, 256>>>(hiddens, BATCH * CORE);
    prep_bias<<<(2 * CORE + OUT_PAD + 255) / 256, 256>>>(bi, ebi, bc, ebc, bo, ebo);
    prep_w_t<<<dim3(IN_SZ / 32, CORE / 32), tb>>>(Wi, ei, (int8_t*)pWiT, (__half*)pWiTh, IN_SZ, CORE);
    prep_w_t<<<dim3(CORE / 32, CORE / 32), tb>>>(Wc, ec, (int8_t*)pWcT, (__half*)pWcTh, CORE, CORE);
    prep_w_t<<<dim3(CORE / 32, OUT_PAD / 32), tb>>>(Wo, eo, (int8_t*)pWoT, (__half*)pWoTh, CORE, OUT_N);

    dim3 g1(CORE / 128, BATCH / 128), g3(OUT_PAD / 128, BATCH / 128);
    // layer 1
    gemm_f16<1><<<g1, 256>>>((const __half*)pinH, (const __half*)pWiTh, (const int*)pbi,
                             (__half*)pA2h, nullptr, (const int8_t*)ph8, IN_SZ, mode_out);
    gemm_s8<1><<<g1, 256>>>((const int8_t*)pin8, (const int8_t*)pWiT, (const int*)pbi,
                            (int8_t*)pA2, nullptr, (const int8_t*)ph8, IN_SZ, mode_out);
    // NOTE: f16 L1 writes A2h; s8 L1 writes A2 — but L1 epilogue must ALSO feed the
    // other path? No: flag is fixed for the whole launch; each layer's input buffer
    // matches its own path.
    // layer 2
    gemm_f16<2><<<g1, 256>>>((const __half*)pA2h, (const __half*)pWcTh, (const int*)pbc,
                             (__half*)pH2h, d_out, nullptr, CORE, mode_out);
    gemm_s8<2><<<g1, 256>>>((const int8_t*)pA2, (const int8_t*)pWcT, (const int*)pbc,
                            (int8_t*)pH2, d_out, nullptr, CORE, mode_out);
    // layer 3
    gemm_f16<3><<<g3, 256>>>((const __half*)pH2h, (const __half*)pWoTh, (const int*)pbo,
                             nullptr, d_out, nullptr, CORE, mode_out);
    gemm_s8<3><<<g3, 256>>>((const int8_t*)pH2, (const int8_t*)pWoT, (const int*)pbo,
                            nullptr, d_out, nullptr, CORE, mode_out);
}

// round 11
// speedup vs baseline: 1.0233x; 1.0233x over previous
#include <cuda_runtime.h>
#include <cuda_bf16.h>
#include <stdint.h>
#include <math.h>

#define IN_SZ   3072
#define CORE    1024
#define OUT_N   100
#define OUT_PAD 128
#define BATCH   8192
#define LDSROW  80
#define STAGES  3

__device__ int g_mode;  // input dtype: 0=int8(packed), 1=f32, 2=i32, 3=bf16

__device__ __align__(16) int8_t g_WiT[CORE * IN_SZ];
__device__ __align__(16) int8_t g_WcT[CORE * CORE];
__device__ __align__(16) int8_t g_WoT[OUT_PAD * CORE];
__device__ __align__(16) int    g_bi[CORE];
__device__ __align__(16) int    g_bc[CORE];
__device__ __align__(16) int    g_bo[OUT_PAD];
__device__ __align__(16) int8_t g_in8[(size_t)BATCH * IN_SZ];   // used only if mode!=0
__device__ __align__(16) int8_t g_h8[(size_t)BATCH * CORE];     // used only if mode!=0
__device__ __align__(16) int8_t g_A2[(size_t)BATCH * CORE];
__device__ __align__(16) int8_t g_H2[(size_t)BATCH * CORE];

__device__ __forceinline__ uint32_t smem_u32(const void* p) {
    uint32_t a;
    asm("{ .reg .u64 t; cvta.to.shared.u64 t, %1; cvt.u32.u64 %0, t; }" : "=r"(a) : "l"(p));
    return a;
}
__device__ __forceinline__ void cpasync16(unsigned dst, const void* src) {
    asm volatile("cp.async.cg.shared.global [%0], [%1], 16;" :: "r"(dst), "l"(src));
}
__device__ __forceinline__ int ldval(const void* src, long i, int m) {
    if (m == 0) return (int)((const int8_t*)src)[i];
    if (m == 1) return (int)((const float*)src)[i];
    if (m == 2) return ((const int*)src)[i];
    return (int)__bfloat162float(((const __nv_bfloat16*)src)[i]);
}

// launch 0: dtype detection
__global__ void detect_mode(const void* w, int unit) {
    if (unit == 2) { if (threadIdx.x == 0) g_mode = 3; return; }
    unsigned r = ((const unsigned*)w)[threadIdx.x * 101];
    int vi = (int)r;
    bool okI = (vi >= -10 && vi <= 10);
    float f = __int_as_float(r);
    bool okF = (isfinite(f) && f == truncf(f) && fabsf(f) <= 10.0f &&
                (f == 0.0f || fabsf(f) >= 1.0f));
    bool okB = true;
    for (int h = 0; h < 2; h++) {
        unsigned hf = (h == 0) ? (r & 0xFFFFu) : (r >> 16);
        float fb = __int_as_float(hf << 16);
        if (!(isfinite(fb) && fb == truncf(fb) && fabsf(fb) <= 10.0f &&
              (fb == 0.0f || fabsf(fb) >= 1.0f))) okB = false;
    }
    int aI = __syncthreads_and((int)okI);
    int aF = __syncthreads_and((int)okF);
    int aB = __syncthreads_and((int)okB);
    if (threadIdx.x == 0)
        g_mode = (unit == 4) ? (aI ? 2 : 1) : (aI ? 2 : (aF ? 1 : (aB ? 3 : 0)));
}

// launch 1: activation conversion (no-op when mode==0: gemm reads raw buffers)
__global__ void conv_acts(const void* __restrict__ inp, const void* __restrict__ hid) {
    const int m = g_mode;
    if (m == 0) return;
    long i = (long)blockIdx.x * blockDim.x + threadIdx.x;
    const long NI = (long)BATCH * IN_SZ;
    if (i < NI) g_in8[i] = (int8_t)ldval(inp, i, m);
    else {
        long j = i - NI;
        if (j < (long)BATCH * CORE) g_h8[j] = (int8_t)ldval(hid, j, m);
    }
}

// launch 2: all weight transposes + biases, fused. block=(32,8).
#define TWI 3072   // (3072/32)*(1024/32)
#define TWC 1024   // (1024/32)*(1024/32)
#define TWO 128    // (1024/32)*(128/32)
__global__ void prep_wb(const void* __restrict__ Wi, const void* __restrict__ ei,
                        const void* __restrict__ Wc, const void* __restrict__ ec,
                        const void* __restrict__ Wo, const void* __restrict__ eo,
                        const void* __restrict__ bi, const void* __restrict__ ebi,
                        const void* __restrict__ bc, const void* __restrict__ ebc,
                        const void* __restrict__ bo, const void* __restrict__ ebo) {
    const int m = g_mode;
    const int b = blockIdx.x;
    const int tx = threadIdx.x, ty = threadIdx.y;
    const void *W, *E;
    int8_t* dst;
    int Kdim, Ncols, kt, nt;
    if (b < TWI) {
        W = Wi; E = ei; dst = g_WiT; Kdim = IN_SZ; Ncols = CORE;
        kt = b % (IN_SZ / 32); nt = b / (IN_SZ / 32);
    } else if (b < TWI + TWC) {
        int r = b - TWI;
        W = Wc; E = ec; dst = g_WcT; Kdim = CORE; Ncols = CORE;
        kt = r % 32; nt = r / 32;
    } else if (b < TWI + TWC + TWO) {
        int r = b - TWI - TWC;
        W = Wo; E = eo; dst = g_WoT; Kdim = CORE; Ncols = OUT_N;
        kt = r % 32; nt = r / 32;
    } else {
        int t = (b - TWI - TWC - TWO) * 256 + ty * 32 + tx;
        if (t < CORE) g_bi[t] = (int)(int8_t)(ldval(bi, t, m) + ldval(ebi, t, m));
        else if (t < 2 * CORE) {
            int i = t - CORE;
            g_bc[i] = (int)(int8_t)(ldval(bc, i, m) + ldval(ebc, i, m));
        } else if (t < 2 * CORE + OUT_PAD) {
            int i = t - 2 * CORE;
            g_bo[i] = (i < OUT_N) ? (int)(int8_t)(ldval(bo, i, m) + ldval(ebo, i, m)) : 0;
        }
        return;
    }
    __shared__ int8_t s[32][33];
    const int kb = kt * 32, nb = nt * 32;
#pragma unroll
    for (int i = 0; i < 32; i += 8) {
        int k = kb + ty + i, n = nb + tx;
        int8_t v = 0;
        if (n < Ncols) {
            long idx = (long)k * Ncols + n;
            v = (int8_t)(ldval(W, idx, m) + ldval(E, idx, m));
        }
        s[ty + i][tx] = v;
    }
    __syncthreads();
#pragma unroll
    for (int i = 0; i < 32; i += 8) {
        int n = nb + ty + i, k = kb + tx;
        dst[(size_t)n * Kdim + k] = s[tx][ty + i];
    }
}

template <int LAYER>
__device__ __forceinline__ void epi_store(int m, int n, int v, const int* bias,
                                          int8_t* Cs, void* Dout, const int8_t* H,
                                          int mode_out) {
    int8_t r = (int8_t)(v + bias[n]);
    if (LAYER == 1) {
        r = (int8_t)(r + H[(size_t)m * CORE + n]);
        Cs[(size_t)m * CORE + n] = r;
    } else if (LAYER == 2) {
        Cs[(size_t)m * CORE + n] = r;
        long oi = (long)m * CORE + n;
        if (mode_out == 3) ((__nv_bfloat16*)Dout)[oi] = __float2bfloat16((float)r);
        else               ((float*)Dout)[oi] = (float)r;
    } else {
        if (n < OUT_N) {
            long oi = (long)BATCH * CORE + (long)m * OUT_N + n;
            if (mode_out == 3) ((__nv_bfloat16*)Dout)[oi] = __float2bfloat16((float)r);
            else               ((float*)Dout)[oi] = (float)r;
        }
    }
}

// ---------------- s8 mma GEMM, 3-stage cp.async pipeline ----------------
// BM=BN=128, BK=64B. rawA/convA selected by g_mode (layer 1 only).
template <int LAYER>
__global__ void __launch_bounds__(256, 2)
gemm_s8(const int8_t* __restrict__ rawA, const int8_t* __restrict__ convA,
        const int8_t* __restrict__ Bt, const int* __restrict__ bias,
        int8_t* __restrict__ Cs, void* __restrict__ Dout,
        const int8_t* __restrict__ rawH, const int8_t* __restrict__ convH,
        int K, int mode_out) {
    __shared__ __align__(16) int8_t sA[STAGES][128 * LDSROW];
    __shared__ __align__(16) int8_t sB[STAGES][128 * LDSROW];

    const int8_t* A = (LAYER == 1 && g_mode != 0) ? convA : rawA;
    const int8_t* H = (LAYER == 1 && g_mode != 0) ? convH : rawH;

    const int tid = threadIdx.x, lane = tid & 31, wid = tid >> 5;
    const int wm = (wid & 1) * 64, wn = (wid >> 1) * 32;
    const int m0 = blockIdx.y * 128, n0 = blockIdx.x * 128;
    const int row1 = tid >> 2, row2 = row1 + 64, seg = (tid & 3) * 16;

    const int8_t* gA1 = A + (size_t)(m0 + row1) * K + seg;
    const int8_t* gA2 = A + (size_t)(m0 + row2) * K + seg;
    const int8_t* gB1 = Bt + (size_t)(n0 + row1) * K + seg;
    const int8_t* gB2 = Bt + (size_t)(n0 + row2) * K + seg;
    const unsigned uA0 = smem_u32(&sA[0][0]), uB0 = smem_u32(&sB[0][0]);
    const unsigned dA1 = row1 * LDSROW + seg, dA2 = row2 * LDSROW + seg;
    const unsigned stageSz = 128 * LDSROW;

    int acc[4][4][4];
#pragma unroll
    for (int a = 0; a < 4; a++)
#pragma unroll
        for (int b = 0; b < 4; b++)
#pragma unroll
            for (int c = 0; c < 4; c++) acc[a][b][c] = 0;

    const int nk = K >> 6;

#define LOADT(st, kt)                                                   \
    do {                                                                \
        const unsigned _d = (st) * stageSz;                             \
        const int _o = (kt) << 6;                                       \
        cpasync16(uA0 + _d + dA1, gA1 + _o);                            \
        cpasync16(uA0 + _d + dA2, gA2 + _o);                            \
        cpasync16(uB0 + _d + dA1, gB1 + _o);                            \
        cpasync16(uB0 + _d + dA2, gB2 + _o);                            \
        asm volatile("cp.async.commit_group;");                         \
    } while (0)

    LOADT(0, 0);
    LOADT(1, 1);

    for (int kt = 0; kt < nk; kt++) {
        const int cur = kt % STAGES;
        asm volatile("cp.async.wait_group 1;");   // stage kt complete
        __syncthreads();                          // all done with stage (kt-1)
        if (kt + 2 < nk) LOADT((kt + 2) % STAGES, kt + 2);
        const unsigned ab = uA0 + cur * stageSz, bb = uB0 + cur * stageSz;
#pragma unroll
        for (int ks = 0; ks < 64; ks += 32) {
            uint32_t af[4][4], bf[4][2];
#pragma unroll
            for (int mf = 0; mf < 4; mf++) {
                const unsigned p = ab + (wm + mf * 16 + (lane & 15)) * LDSROW + ks + ((lane >> 4) << 4);
                asm volatile("ldmatrix.sync.aligned.m8n8.x4.shared.b16 {%0,%1,%2,%3}, [%4];"
                             : "=r"(af[mf][0]), "=r"(af[mf][1]), "=r"(af[mf][2]), "=r"(af[mf][3]) : "r"(p));
            }
#pragma unroll
            for (int nf = 0; nf < 4; nf++) {
                const unsigned p = bb + (wn + nf * 8 + (lane & 7)) * LDSROW + ks + (((lane >> 3) & 1) << 4);
                asm volatile("ldmatrix.sync.aligned.m8n8.x2.shared.b16 {%0,%1}, [%2];"
                             : "=r"(bf[nf][0]), "=r"(bf[nf][1]) : "r"(p));
            }
#pragma unroll
            for (int mf = 0; mf < 4; mf++)
#pragma unroll
                for (int nf = 0; nf < 4; nf++)
                    asm volatile("mma.sync.aligned.m16n8k32.row.col.s32.s8.s8.s32 "
                                 "{%0,%1,%2,%3}, {%4,%5,%6,%7}, {%8,%9}, {%0,%1,%2,%3};"
                                 : "+r"(acc[mf][nf][0]), "+r"(acc[mf][nf][1]),
                                   "+r"(acc[mf][nf][2]), "+r"(acc[mf][nf][3])
                                 : "r"(af[mf][0]), "r"(af[mf][1]), "r"(af[mf][2]), "r"(af[mf][3]),
                                   "r"(bf[nf][0]), "r"(bf[nf][1]));
        }
    }
#undef LOADT
    asm volatile("cp.async.wait_group 0;");

    const int r = lane >> 2, cq = (lane & 3) * 2;
#pragma unroll
    for (int mf = 0; mf < 4; mf++)
#pragma unroll
        for (int nf = 0; nf < 4; nf++)
#pragma unroll
            for (int half = 0; half < 2; half++) {
                const int m = m0 + wm + mf * 16 + r + half * 8;
                const int n = n0 + wn + nf * 8 + cq;
                epi_store<LAYER>(m, n,     acc[mf][nf][half * 2 + 0], bias, Cs, Dout, H, mode_out);
                epi_store<LAYER>(m, n + 1, acc[mf][nf][half * 2 + 1], bias, Cs, Dout, H, mode_out);
            }
}

extern "C" void kernel_launch(void* const* d_in, const int* in_sizes, int n_in,
                              void* d_out, int out_size) {
    int idx[64];
    int cnt = (n_in < 64) ? n_in : 64;
    for (int i = 0; i < cnt; i++) idx[i] = i;
    for (int a = 1; a < cnt; a++) {
        int t = idx[a], b = a - 1;
        while (b >= 0 && in_sizes[idx[b]] < in_sizes[t]) { idx[b + 1] = idx[b]; b--; }
        idx[b + 1] = t;
    }
    const void *inputs = 0, *hiddens = 0, *Wi = 0, *ei = 0, *Wc = 0, *ec = 0;
    const void *Wo = 0, *eo = 0, *bo = 0, *ebo = 0;
    const void *bi = 0, *bc = 0, *ebi = 0, *ebc = 0;
    long unit = 1;
    if (cnt >= 14) {
        inputs = d_in[idx[0]]; hiddens = d_in[idx[1]];
        Wi = d_in[idx[2]]; ei = d_in[idx[3]];
        Wc = d_in[idx[4]]; ec = d_in[idx[5]];
        Wo = d_in[idx[6]]; eo = d_in[idx[7]];
        bo = d_in[idx[12]]; ebo = d_in[idx[13]];
        bool alpha = (idx[4] < idx[2]);
        if (alpha) { bc = d_in[idx[8]]; bi = d_in[idx[9]]; ebc = d_in[idx[10]]; ebi = d_in[idx[11]]; }
        else       { bi = d_in[idx[8]]; bc = d_in[idx[9]]; ebi = d_in[idx[10]]; ebc = d_in[idx[11]]; }
        unit = (long)in_sizes[idx[0]] / ((long)BATCH * IN_SZ);
        if (unit < 1) unit = 1;
    } else {
        Wi = d_in[0]; bi = d_in[1]; Wc = d_in[2]; bc = d_in[3];
        Wo = d_in[4]; bo = d_in[5]; ei = d_in[6]; ebi = d_in[7];
        ec = d_in[8]; ebc = d_in[9]; eo = d_in[10]; ebo = d_in[11];
        inputs = d_in[12]; hiddens = d_in[13];
    }
    const long total_out = (long)BATCH * CORE + (long)BATCH * OUT_N;
    int mode_out = 1;
    if ((long)out_size == 2 * total_out) mode_out = 3;

    void *pWiT, *pWcT, *pWoT, *pbi, *pbc, *pbo, *pin8, *ph8, *pA2, *pH2;
    cudaGetSymbolAddress(&pWiT, g_WiT);
    cudaGetSymbolAddress(&pWcT, g_WcT);
    cudaGetSymbolAddress(&pWoT, g_WoT);
    cudaGetSymbolAddress(&pbi, g_bi);
    cudaGetSymbolAddress(&pbc, g_bc);
    cudaGetSymbolAddress(&pbo, g_bo);
    cudaGetSymbolAddress(&pin8, g_in8);
    cudaGetSymbolAddress(&ph8, g_h8);
    cudaGetSymbolAddress(&pA2, g_A2);
    cudaGetSymbolAddress(&pH2, g_H2);

    // launches: 0=detect, 1=conv_acts, 2=prep_wb, 3=gemm1 (<- ncu -s5 profiles this)
    detect_mode<<<1, 256>>>(Wi, (int)unit);
    {
        long tot = (long)BATCH * IN_SZ + (long)BATCH * CORE;
        conv_acts<<<(unsigned)((tot + 255) / 256), 256>>>(inputs, hiddens);
    }
    prep_wb<<<TWI + TWC + TWO + 9, dim3(32, 8)>>>(Wi, ei, Wc, ec, Wo, eo,
                                                  bi, ebi, bc, ebc, bo, ebo);

    dim3 g1(CORE / 128, BATCH / 128), g3(OUT_PAD / 128, BATCH / 128);
    gemm_s8<1><<<g1, 256>>>((const int8_t*)inputs, (const int8_t*)pin8,
                            (const int8_t*)pWiT, (const int*)pbi,
                            (int8_t*)pA2, nullptr,
                            (const int8_t*)hiddens, (const int8_t*)ph8,
                            IN_SZ, mode_out);
    gemm_s8<2><<<g1, 256>>>((const int8_t*)pA2, (const int8_t*)pA2,
                            (const int8_t*)pWcT, (const int*)pbc,
                            (int8_t*)pH2, d_out, nullptr, nullptr,
                            CORE, mode_out);
    gemm_s8<3><<<g3, 256>>>((const int8_t*)pH2, (const int8_t*)pH2,
                            (const int8_t*)pWoT, (const int*)pbo,
                            nullptr, d_out, nullptr, nullptr,
                            CORE, mode_out);
}

// round 12
// speedup vs baseline: 1.0605x; 1.0363x over previous
#include <cuda_runtime.h>
#include <cuda_bf16.h>
#include <stdint.h>
#include <math.h>

#define IN_SZ   3072
#define CORE    1024
#define OUT_N   100
#define OUT_PAD 128
#define BATCH   8192
#define STAGES  3
#define STG_OP  16384                 // bytes per stage per operand (128 rows x 128B)
#define SMEM_BYTES (STAGES * 2 * STG_OP)

__device__ int g_mode;  // input dtype: 0=int8(packed), 1=f32, 2=i32, 3=bf16

__device__ __align__(16) int8_t g_WiT[CORE * IN_SZ];
__device__ __align__(16) int8_t g_WcT[CORE * CORE];
__device__ __align__(16) int8_t g_WoT[OUT_PAD * CORE];
__device__ __align__(16) int    g_bi[CORE];
__device__ __align__(16) int    g_bc[CORE];
__device__ __align__(16) int    g_bo[OUT_PAD];
__device__ __align__(16) int8_t g_in8[(size_t)BATCH * IN_SZ];
__device__ __align__(16) int8_t g_h8[(size_t)BATCH * CORE];
__device__ __align__(16) int8_t g_A2[(size_t)BATCH * CORE];
__device__ __align__(16) int8_t g_H2[(size_t)BATCH * CORE];

__device__ __forceinline__ uint32_t smem_u32(const void* p) {
    uint32_t a;
    asm("{ .reg .u64 t; cvta.to.shared.u64 t, %1; cvt.u32.u64 %0, t; }" : "=r"(a) : "l"(p));
    return a;
}
__device__ __forceinline__ void cpasync16(unsigned dst, const void* src) {
    asm volatile("cp.async.cg.shared.global [%0], [%1], 16;" :: "r"(dst), "l"(src));
}
__device__ __forceinline__ int ldval(const void* src, long i, int m) {
    if (m == 0) return (int)((const int8_t*)src)[i];
    if (m == 1) return (int)((const float*)src)[i];
    if (m == 2) return ((const int*)src)[i];
    return (int)__bfloat162float(((const __nv_bfloat16*)src)[i]);
}

__global__ void detect_mode(const void* w, int unit) {
    if (unit == 2) { if (threadIdx.x == 0) g_mode = 3; return; }
    unsigned r = ((const unsigned*)w)[threadIdx.x * 101];
    int vi = (int)r;
    bool okI = (vi >= -10 && vi <= 10);
    float f = __int_as_float(r);
    bool okF = (isfinite(f) && f == truncf(f) && fabsf(f) <= 10.0f &&
                (f == 0.0f || fabsf(f) >= 1.0f));
    bool okB = true;
    for (int h = 0; h < 2; h++) {
        unsigned hf = (h == 0) ? (r & 0xFFFFu) : (r >> 16);
        float fb = __int_as_float(hf << 16);
        if (!(isfinite(fb) && fb == truncf(fb) && fabsf(fb) <= 10.0f &&
              (fb == 0.0f || fabsf(fb) >= 1.0f))) okB = false;
    }
    int aI = __syncthreads_and((int)okI);
    int aF = __syncthreads_and((int)okF);
    int aB = __syncthreads_and((int)okB);
    if (threadIdx.x == 0)
        g_mode = (unit == 4) ? (aI ? 2 : 1) : (aI ? 2 : (aF ? 1 : (aB ? 3 : 0)));
}

__global__ void conv_acts(const void* __restrict__ inp, const void* __restrict__ hid) {
    const int m = g_mode;
    if (m == 0) return;
    long i = (long)blockIdx.x * blockDim.x + threadIdx.x;
    const long NI = (long)BATCH * IN_SZ;
    if (i < NI) g_in8[i] = (int8_t)ldval(inp, i, m);
    else {
        long j = i - NI;
        if (j < (long)BATCH * CORE) g_h8[j] = (int8_t)ldval(hid, j, m);
    }
}

#define TWI 3072
#define TWC 1024
#define TWO 128
__global__ void prep_wb(const void* __restrict__ Wi, const void* __restrict__ ei,
                        const void* __restrict__ Wc, const void* __restrict__ ec,
                        const void* __restrict__ Wo, const void* __restrict__ eo,
                        const void* __restrict__ bi, const void* __restrict__ ebi,
                        const void* __restrict__ bc, const void* __restrict__ ebc,
                        const void* __restrict__ bo, const void* __restrict__ ebo) {
    const int m = g_mode;
    const int b = blockIdx.x;
    const int tx = threadIdx.x, ty = threadIdx.y;
    const void *W, *E;
    int8_t* dst;
    int Kdim, Ncols, kt, nt;
    if (b < TWI) {
        W = Wi; E = ei; dst = g_WiT; Kdim = IN_SZ; Ncols = CORE;
        kt = b % (IN_SZ / 32); nt = b / (IN_SZ / 32);
    } else if (b < TWI + TWC) {
        int r = b - TWI;
        W = Wc; E = ec; dst = g_WcT; Kdim = CORE; Ncols = CORE;
        kt = r % 32; nt = r / 32;
    } else if (b < TWI + TWC + TWO) {
        int r = b - TWI - TWC;
        W = Wo; E = eo; dst = g_WoT; Kdim = CORE; Ncols = OUT_N;
        kt = r % 32; nt = r / 32;
    } else {
        int t = (b - TWI - TWC - TWO) * 256 + ty * 32 + tx;
        if (t < CORE) g_bi[t] = (int)(int8_t)(ldval(bi, t, m) + ldval(ebi, t, m));
        else if (t < 2 * CORE) {
            int i = t - CORE;
            g_bc[i] = (int)(int8_t)(ldval(bc, i, m) + ldval(ebc, i, m));
        } else if (t < 2 * CORE + OUT_PAD) {
            int i = t - 2 * CORE;
            g_bo[i] = (i < OUT_N) ? (int)(int8_t)(ldval(bo, i, m) + ldval(ebo, i, m)) : 0;
        }
        return;
    }
    __shared__ int8_t s[32][33];
    const int kb = kt * 32, nb = nt * 32;
#pragma unroll
    for (int i = 0; i < 32; i += 8) {
        int k = kb + ty + i, n = nb + tx;
        int8_t v = 0;
        if (n < Ncols) {
            long idx = (long)k * Ncols + n;
            v = (int8_t)(ldval(W, idx, m) + ldval(E, idx, m));
        }
        s[ty + i][tx] = v;
    }
    __syncthreads();
#pragma unroll
    for (int i = 0; i < 32; i += 8) {
        int n = nb + ty + i, k = kb + tx;
        dst[(size_t)n * Kdim + k] = s[tx][ty + i];
    }
}

template <int LAYER>
__device__ __forceinline__ void epi_store(int m, int n, int v, const int* bias,
                                          int8_t* Cs, void* Dout, const int8_t* H,
                                          int mode_out) {
    int8_t r = (int8_t)(v + bias[n]);
    if (LAYER == 1) {
        r = (int8_t)(r + H[(size_t)m * CORE + n]);
        Cs[(size_t)m * CORE + n] = r;
    } else if (LAYER == 2) {
        Cs[(size_t)m * CORE + n] = r;
        long oi = (long)m * CORE + n;
        if (mode_out == 3) ((__nv_bfloat16*)Dout)[oi] = __float2bfloat16((float)r);
        else               ((float*)Dout)[oi] = (float)r;
    } else {
        if (n < OUT_N) {
            long oi = (long)BATCH * CORE + (long)m * OUT_N + n;
            if (mode_out == 3) ((__nv_bfloat16*)Dout)[oi] = __float2bfloat16((float)r);
            else               ((float*)Dout)[oi] = (float)r;
        }
    }
}

// ---------------- s8 mma GEMM: BM=BN=128, BK=128B, swizzled smem, 3-stage ----------------
template <int LAYER>
__global__ void __launch_bounds__(256, 2)
gemm_s8(const int8_t* __restrict__ rawA, const int8_t* __restrict__ convA,
        const int8_t* __restrict__ Bt, const int* __restrict__ bias,
        int8_t* __restrict__ Cs, void* __restrict__ Dout,
        const int8_t* __restrict__ rawH, const int8_t* __restrict__ convH,
        int K, int mode_out) {
    extern __shared__ __align__(16) int8_t dyn[];
    const int8_t* A = (LAYER == 1 && g_mode != 0) ? convA : rawA;
    const int8_t* H = (LAYER == 1 && g_mode != 0) ? convH : rawH;

    const int tid = threadIdx.x, lane = tid & 31, wid = tid >> 5;
    const int wm = (wid & 1) * 64, wn = (wid >> 1) * 32;
    const int m0 = blockIdx.y * 128, n0 = blockIdx.x * 128;

    // loader geometry: 1024 16B-chunks per operand per tile; 4/thread
    const int r0  = tid >> 3;            // base row 0..31
    const int seg = (tid & 7) << 4;      // 16B column segment within 128B row
    const int swz = seg ^ ((r0 & 7) << 4);

    const unsigned uS = smem_u32(dyn);   // sA stages at 0, sB at STAGES*STG_OP
    const unsigned uB = uS + STAGES * STG_OP;

    const int8_t* gA = A + (size_t)(m0 + r0) * K + seg;
    const int8_t* gB = Bt + (size_t)(n0 + r0) * K + seg;
    const long rowStride32 = 32L * K;

    int acc[4][4][4];
#pragma unroll
    for (int a = 0; a < 4; a++)
#pragma unroll
        for (int b = 0; b < 4; b++)
#pragma unroll
            for (int c = 0; c < 4; c++) acc[a][b][c] = 0;

    const int nk = K >> 7;   // 128B K-tiles

#define LOADT(st, kt)                                                     \
    do {                                                                  \
        const unsigned _a = uS + (st) * STG_OP;                           \
        const unsigned _b = uB + (st) * STG_OP;                           \
        const long _o = (long)((kt) << 7);                                \
        _Pragma("unroll")                                                 \
        for (int _i = 0; _i < 4; _i++) {                                  \
            const unsigned _d = (_i * 32 + r0) * 128 + swz;               \
            cpasync16(_a + _d, gA + _o + _i * rowStride32);               \
            cpasync16(_b + _d, gB + _o + _i * rowStride32);               \
        }                                                                 \
        asm volatile("cp.async.commit_group;");                           \
    } while (0)

    LOADT(0, 0);
    if (nk > 1) LOADT(1, 1);

    for (int kt = 0; kt < nk; kt++) {
        const int cur = kt % STAGES;
        asm volatile("cp.async.wait_group 1;");
        __syncthreads();
        if (kt + 2 < nk) LOADT((kt + 2) % STAGES, kt + 2);
        const unsigned ab = uS + cur * STG_OP;
        const unsigned bb = uB + cur * STG_OP;
#pragma unroll
        for (int ks = 0; ks < 128; ks += 32) {
            uint32_t af[4][4], bf[4][2];
#pragma unroll
            for (int mf = 0; mf < 4; mf++) {
                const int ra = wm + mf * 16 + (lane & 15);
                const int ca = ks + ((lane >> 4) << 4);
                const unsigned p = ab + ra * 128 + (ca ^ ((ra & 7) << 4));
                asm volatile("ldmatrix.sync.aligned.m8n8.x4.shared.b16 {%0,%1,%2,%3}, [%4];"
                             : "=r"(af[mf][0]), "=r"(af[mf][1]), "=r"(af[mf][2]), "=r"(af[mf][3]) : "r"(p));
            }
#pragma unroll
            for (int nf = 0; nf < 4; nf++) {
                const int rb = wn + nf * 8 + (lane & 7);
                const int cb = ks + (((lane >> 3) & 1) << 4);
                const unsigned p = bb + rb * 128 + (cb ^ ((rb & 7) << 4));
                asm volatile("ldmatrix.sync.aligned.m8n8.x2.shared.b16 {%0,%1}, [%2];"
                             : "=r"(bf[nf][0]), "=r"(bf[nf][1]) : "r"(p));
            }
#pragma unroll
            for (int mf = 0; mf < 4; mf++)
#pragma unroll
                for (int nf = 0; nf < 4; nf++)
                    asm volatile("mma.sync.aligned.m16n8k32.row.col.s32.s8.s8.s32 "
                                 "{%0,%1,%2,%3}, {%4,%5,%6,%7}, {%8,%9}, {%0,%1,%2,%3};"
                                 : "+r"(acc[mf][nf][0]), "+r"(acc[mf][nf][1]),
                                   "+r"(acc[mf][nf][2]), "+r"(acc[mf][nf][3])
                                 : "r"(af[mf][0]), "r"(af[mf][1]), "r"(af[mf][2]), "r"(af[mf][3]),
                                   "r"(bf[nf][0]), "r"(bf[nf][1]));
        }
    }
#undef LOADT
    asm volatile("cp.async.wait_group 0;");

    const int r = lane >> 2, cq = (lane & 3) * 2;
#pragma unroll
    for (int mf = 0; mf < 4; mf++)
#pragma unroll
        for (int nf = 0; nf < 4; nf++)
#pragma unroll
            for (int half = 0; half < 2; half++) {
                const int m = m0 + wm + mf * 16 + r + half * 8;
                const int n = n0 + wn + nf * 8 + cq;
                epi_store<LAYER>(m, n,     acc[mf][nf][half * 2 + 0], bias, Cs, Dout, H, mode_out);
                epi_store<LAYER>(m, n + 1, acc[mf][nf][half * 2 + 1], bias, Cs, Dout, H, mode_out);
            }
}

extern "C" void kernel_launch(void* const* d_in, const int* in_sizes, int n_in,
                              void* d_out, int out_size) {
    int idx[64];
    int cnt = (n_in < 64) ? n_in : 64;
    for (int i = 0; i < cnt; i++) idx[i] = i;
    for (int a = 1; a < cnt; a++) {
        int t = idx[a], b = a - 1;
        while (b >= 0 && in_sizes[idx[b]] < in_sizes[t]) { idx[b + 1] = idx[b]; b--; }
        idx[b + 1] = t;
    }
    const void *inputs = 0, *hiddens = 0, *Wi = 0, *ei = 0, *Wc = 0, *ec = 0;
    const void *Wo = 0, *eo = 0, *bo = 0, *ebo = 0;
    const void *bi = 0, *bc = 0, *ebi = 0, *ebc = 0;
    long unit = 1;
    if (cnt >= 14) {
        inputs = d_in[idx[0]]; hiddens = d_in[idx[1]];
        Wi = d_in[idx[2]]; ei = d_in[idx[3]];
        Wc = d_in[idx[4]]; ec = d_in[idx[5]];
        Wo = d_in[idx[6]]; eo = d_in[idx[7]];
        bo = d_in[idx[12]]; ebo = d_in[idx[13]];
        bool alpha = (idx[4] < idx[2]);
        if (alpha) { bc = d_in[idx[8]]; bi = d_in[idx[9]]; ebc = d_in[idx[10]]; ebi = d_in[idx[11]]; }
        else       { bi = d_in[idx[8]]; bc = d_in[idx[9]]; ebi = d_in[idx[10]]; ebc = d_in[idx[11]]; }
        unit = (long)in_sizes[idx[0]] / ((long)BATCH * IN_SZ);
        if (unit < 1) unit = 1;
    } else {
        Wi = d_in[0]; bi = d_in[1]; Wc = d_in[2]; bc = d_in[3];
        Wo = d_in[4]; bo = d_in[5]; ei = d_in[6]; ebi = d_in[7];
        ec = d_in[8]; ebc = d_in[9]; eo = d_in[10]; ebo = d_in[11];
        inputs = d_in[12]; hiddens = d_in[13];
    }
    const long total_out = (long)BATCH * CORE + (long)BATCH * OUT_N;
    int mode_out = 1;
    if ((long)out_size == 2 * total_out) mode_out = 3;

    void *pWiT, *pWcT, *pWoT, *pbi, *pbc, *pbo, *pin8, *ph8, *pA2, *pH2;
    cudaGetSymbolAddress(&pWiT, g_WiT);
    cudaGetSymbolAddress(&pWcT, g_WcT);
    cudaGetSymbolAddress(&pWoT, g_WoT);
    cudaGetSymbolAddress(&pbi, g_bi);
    cudaGetSymbolAddress(&pbc, g_bc);
    cudaGetSymbolAddress(&pbo, g_bo);
    cudaGetSymbolAddress(&pin8, g_in8);
    cudaGetSymbolAddress(&ph8, g_h8);
    cudaGetSymbolAddress(&pA2, g_A2);
    cudaGetSymbolAddress(&pH2, g_H2);

    static int s_attr_done = 0;
    if (!s_attr_done) {
        cudaFuncSetAttribute(gemm_s8<1>, cudaFuncAttributeMaxDynamicSharedMemorySize, SMEM_BYTES);
        cudaFuncSetAttribute(gemm_s8<2>, cudaFuncAttributeMaxDynamicSharedMemorySize, SMEM_BYTES);
        cudaFuncSetAttribute(gemm_s8<3>, cudaFuncAttributeMaxDynamicSharedMemorySize, SMEM_BYTES);
        s_attr_done = 1;
    }

    detect_mode<<<1, 256>>>(Wi, (int)unit);
    {
        long tot = (long)BATCH * IN_SZ + (long)BATCH * CORE;
        conv_acts<<<(unsigned)((tot + 255) / 256), 256>>>(inputs, hiddens);
    }
    prep_wb<<<TWI + TWC + TWO + 9, dim3(32, 8)>>>(Wi, ei, Wc, ec, Wo, eo,
                                                  bi, ebi, bc, ebc, bo, ebo);

    dim3 g1(CORE / 128, BATCH / 128), g3(OUT_PAD / 128, BATCH / 128);
    gemm_s8<1><<<g1, 256, SMEM_BYTES>>>((const int8_t*)inputs, (const int8_t*)pin8,
                                        (const int8_t*)pWiT, (const int*)pbi,
                                        (int8_t*)pA2, nullptr,
                                        (const int8_t*)hiddens, (const int8_t*)ph8,
                                        IN_SZ, mode_out);
    gemm_s8<2><<<g1, 256, SMEM_BYTES>>>((const int8_t*)pA2, (const int8_t*)pA2,
                                        (const int8_t*)pWcT, (const int*)pbc,
                                        (int8_t*)pH2, d_out, nullptr, nullptr,
                                        CORE, mode_out);
    gemm_s8<3><<<g3, 256, SMEM_BYTES>>>((const int8_t*)pH2, (const int8_t*)pH2,
                                        (const int8_t*)pWoT, (const int*)pbo,
                                        nullptr, d_out, nullptr, nullptr,
                                        CORE, mode_out);
}